// round 5
// baseline (speedup 1.0000x reference)
#include <cuda_runtime.h>
#include <cuda_bf16.h>
#include <stdint.h>

#define NN     65536
#define HID    1024
#define NCOLS1 3072

// ---------------- scratch (static device globals; allocation-free) ----------
__device__ __nv_bfloat16 g_h_hi[(size_t)NN * HID];
__device__ __nv_bfloat16 g_h_lo[(size_t)NN * HID];
__device__ __nv_bfloat16 g_w1_hi[(size_t)3 * HID * HID];
__device__ __nv_bfloat16 g_w1_lo[(size_t)3 * HID * HID];
__device__ __nv_bfloat16 g_w2_hi[(size_t)HID * HID];
__device__ __nv_bfloat16 g_w2_lo[(size_t)HID * HID];
__device__ float         g_qkv[(size_t)NN * NCOLS1];
__device__ __nv_bfloat16 g_o_hi[(size_t)NN * HID];
__device__ __nv_bfloat16 g_o_lo[(size_t)NN * HID];

// ---------------- split fp32 -> bf16 hi/lo ----------------------------------
__device__ __forceinline__ void split_body(const float* __restrict__ src,
                                           __nv_bfloat16* __restrict__ hi,
                                           __nv_bfloat16* __restrict__ lo,
                                           int n4) {
    int i = blockIdx.x * blockDim.x + threadIdx.x;
    if (i >= n4) return;
    float4 v = ((const float4*)src)[i];
    __nv_bfloat16 h0 = __float2bfloat16_rn(v.x);
    __nv_bfloat16 h1 = __float2bfloat16_rn(v.y);
    __nv_bfloat16 h2 = __float2bfloat16_rn(v.z);
    __nv_bfloat16 h3 = __float2bfloat16_rn(v.w);
    __nv_bfloat16 l0 = __float2bfloat16_rn(v.x - __bfloat162float(h0));
    __nv_bfloat16 l1 = __float2bfloat16_rn(v.y - __bfloat162float(h1));
    __nv_bfloat16 l2 = __float2bfloat16_rn(v.z - __bfloat162float(h2));
    __nv_bfloat16 l3 = __float2bfloat16_rn(v.w - __bfloat162float(h3));
    size_t o = (size_t)2 * i;
    ((__nv_bfloat162*)hi)[o]     = __halves2bfloat162(h0, h1);
    ((__nv_bfloat162*)hi)[o + 1] = __halves2bfloat162(h2, h3);
    ((__nv_bfloat162*)lo)[o]     = __halves2bfloat162(l0, l1);
    ((__nv_bfloat162*)lo)[o + 1] = __halves2bfloat162(l2, l3);
}

__global__ void k_split_h(const float* __restrict__ src) {
    split_body(src, g_h_hi, g_h_lo, NN * HID / 4);
}
__global__ void k_split_w1(const float* __restrict__ src, int seg) {
    size_t off = (size_t)seg * HID * HID;
    split_body(src, g_w1_hi + off, g_w1_lo + off, HID * HID / 4);
}
__global__ void k_split_w2(const float* __restrict__ src) {
    split_body(src, g_w2_hi, g_w2_lo, HID * HID / 4);
}

// ---------------- GEMM (bf16x3, mma.sync m16n8k16, cp.async) ----------------
#define BM 128
#define BN 128
#define BK 32
#define PAD 40                        // halves per smem row (80B, conflict-free)
#define ARR_HALVES (128 * PAD)        // 5120 halves per operand array
#define STAGE_HALVES (4 * ARR_HALVES) // Ah, Al, Bh, Bl
#define SMEM_BYTES (2 * STAGE_HALVES * 2)

__device__ __forceinline__ uint32_t sptr(const void* p) {
    return (uint32_t)__cvta_generic_to_shared(p);
}
__device__ __forceinline__ void cp16(uint32_t dst, const void* src) {
    asm volatile(
        "{\n\t"
        ".reg .u64 gp;\n\t"
        "cvta.to.global.u64 gp, %1;\n\t"
        "cp.async.cg.shared.global [%0], [gp], 16;\n\t"
        "}\n" :: "r"(dst), "l"(src));
}
__device__ __forceinline__ void cp_commit() {
    asm volatile("cp.async.commit_group;\n");
}
__device__ __forceinline__ void cp_wait1() {
    asm volatile("cp.async.wait_group 1;\n");
}
__device__ __forceinline__ void ldsm4(uint32_t* r, const __nv_bfloat16* p) {
    uint32_t a = sptr(p);
    asm volatile("ldmatrix.sync.aligned.m8n8.x4.shared.b16 {%0,%1,%2,%3}, [%4];\n"
                 : "=r"(r[0]), "=r"(r[1]), "=r"(r[2]), "=r"(r[3]) : "r"(a));
}
__device__ __forceinline__ void mma16816(float* c, const uint32_t* a, const uint32_t* b) {
    asm volatile("mma.sync.aligned.m16n8k16.row.col.f32.bf16.bf16.f32 "
                 "{%0,%1,%2,%3}, {%4,%5,%6,%7}, {%8,%9}, {%0,%1,%2,%3};\n"
                 : "+f"(c[0]), "+f"(c[1]), "+f"(c[2]), "+f"(c[3])
                 : "r"(a[0]), "r"(a[1]), "r"(a[2]), "r"(a[3]), "r"(b[0]), "r"(b[1]));
}

__device__ __forceinline__ void load_stage(__nv_bfloat16* sm, int stage,
                                           const __nv_bfloat16* __restrict__ Ah,
                                           const __nv_bfloat16* __restrict__ Al,
                                           const __nv_bfloat16* __restrict__ Bh,
                                           const __nv_bfloat16* __restrict__ Bl,
                                           size_t m0, size_t n0, int kk, int tid) {
    __nv_bfloat16* base = sm + (size_t)stage * STAGE_HALVES;
#pragma unroll
    for (int rep = 0; rep < 2; rep++) {
        int c = tid + rep * 256;          // 512 chunks of 16B per operand tile
        int row = c >> 2;                 // 0..127
        int cc = c & 3;                   // 16B chunk within 64B row
        int so = row * PAD + cc * 8;
        size_t ga = (m0 + row) * HID + kk + cc * 8;
        size_t gb = (n0 + row) * HID + kk + cc * 8;
        cp16(sptr(base + so),                  Ah + ga);
        cp16(sptr(base + ARR_HALVES + so),     Al + ga);
        cp16(sptr(base + 2 * ARR_HALVES + so), Bh + gb);
        cp16(sptr(base + 3 * ARR_HALVES + so), Bl + gb);
    }
}

template <int NC>
__device__ __forceinline__ void gemm_dev(const __nv_bfloat16* __restrict__ Ah,
                                         const __nv_bfloat16* __restrict__ Al,
                                         const __nv_bfloat16* __restrict__ Bh,
                                         const __nv_bfloat16* __restrict__ Bl,
                                         float* __restrict__ C) {
    extern __shared__ __nv_bfloat16 sm[];
    const int tid = threadIdx.x;
    const int lane = tid & 31;
    const int wid = tid >> 5;
    const int warp_m = wid >> 2;   // 0..1  (64 rows each)
    const int warp_n = wid & 3;    // 0..3  (32 cols each)
    const size_t m0 = (size_t)blockIdx.y * BM;
    const size_t n0 = (size_t)blockIdx.x * BN;

    float acc[4][4][4];
#pragma unroll
    for (int mt = 0; mt < 4; mt++)
#pragma unroll
        for (int nt = 0; nt < 4; nt++)
#pragma unroll
            for (int q = 0; q < 4; q++) acc[mt][nt][q] = 0.0f;

    load_stage(sm, 0, Ah, Al, Bh, Bl, m0, n0, 0, tid);
    cp_commit();

    const int KT = HID / BK;   // 32
    for (int kt = 0; kt < KT; kt++) {
        int cur = kt & 1;
        if (kt + 1 < KT) load_stage(sm, cur ^ 1, Ah, Al, Bh, Bl, m0, n0, (kt + 1) * BK, tid);
        cp_commit();
        cp_wait1();
        __syncthreads();

        const __nv_bfloat16* sAh = sm + (size_t)cur * STAGE_HALVES;
        const __nv_bfloat16* sAl = sAh + ARR_HALVES;
        const __nv_bfloat16* sBh = sAh + 2 * ARR_HALVES;
        const __nv_bfloat16* sBl = sAh + 3 * ARR_HALVES;

#pragma unroll
        for (int ks = 0; ks < 2; ks++) {
            uint32_t ah[4][4], al[4][4], bh[4][2], bl[4][2];
            int arow = warp_m * 64 + (lane & 15);
            int acol = ks * 16 + (lane >> 4) * 8;
#pragma unroll
            for (int mt = 0; mt < 4; mt++) {
                ldsm4(ah[mt], sAh + (arow + mt * 16) * PAD + acol);
                ldsm4(al[mt], sAl + (arow + mt * 16) * PAD + acol);
            }
            int brow = warp_n * 32 + ((lane >> 4) << 3) + (lane & 7);
            int bcol = ks * 16 + ((lane >> 3) & 1) * 8;
#pragma unroll
            for (int p = 0; p < 2; p++) {
                uint32_t r[4];
                ldsm4(r, sBh + (brow + p * 16) * PAD + bcol);
                bh[2 * p][0] = r[0]; bh[2 * p][1] = r[1];
                bh[2 * p + 1][0] = r[2]; bh[2 * p + 1][1] = r[3];
                ldsm4(r, sBl + (brow + p * 16) * PAD + bcol);
                bl[2 * p][0] = r[0]; bl[2 * p][1] = r[1];
                bl[2 * p + 1][0] = r[2]; bl[2 * p + 1][1] = r[3];
            }
#pragma unroll
            for (int mt = 0; mt < 4; mt++)
#pragma unroll
                for (int nt = 0; nt < 4; nt++) {
                    mma16816(acc[mt][nt], ah[mt], bh[nt]);   // hi*hi
                    mma16816(acc[mt][nt], ah[mt], bl[nt]);   // hi*lo
                    mma16816(acc[mt][nt], al[mt], bh[nt]);   // lo*hi
                }
        }
        __syncthreads();
    }

    // epilogue
    const int r = lane >> 2;
    const int cq = (lane & 3) * 2;
#pragma unroll
    for (int mt = 0; mt < 4; mt++) {
        size_t row = m0 + warp_m * 64 + mt * 16 + r;
#pragma unroll
        for (int nt = 0; nt < 4; nt++) {
            size_t col = n0 + warp_n * 32 + nt * 8 + cq;
            *(float2*)(C + row * NC + col)       = make_float2(acc[mt][nt][0], acc[mt][nt][1]);
            *(float2*)(C + (row + 8) * NC + col) = make_float2(acc[mt][nt][2], acc[mt][nt][3]);
        }
    }
}

__global__ void __launch_bounds__(256, 1) gemm1_kernel() {
    gemm_dev<NCOLS1>(g_h_hi, g_h_lo, g_w1_hi, g_w1_lo, g_qkv);
}
__global__ void __launch_bounds__(256, 1) gemm2_kernel(float* __restrict__ out) {
    gemm_dev<HID>(g_o_hi, g_o_lo, g_w2_hi, g_w2_lo, out);
}

// ---------------- per-node attention (2 nodes / 128-thread block) ------------
__global__ void __launch_bounds__(128) attn_kernel() {
    __shared__ __align__(16) float Qt[2][64 * 17];   // Qt[d][l], padded
    __shared__ __align__(16) float Ks[2][1024];      // raw K row
    __shared__ __align__(16) float Vp[2][64 * 17];   // Vp[d][g], padded
    __shared__ __align__(16) float Ss[2][16 * 17];   // scores[l][g], padded
    const int tid = threadIdx.x;
    const size_t node0 = (size_t)blockIdx.x * 2;
    const float4* src = (const float4*)(g_qkv + node0 * NCOLS1);

    for (int i = tid; i < 2 * NCOLS1 / 4; i += 128) {
        float4 v = src[i];
        int nd = i / (NCOLS1 / 4);
        int j = (i % (NCOLS1 / 4)) * 4;
        if (j < 1024) {                       // Q: store transposed Qt[d][l]
            int l = j >> 6, d = j & 63;
            Qt[nd][(d + 0) * 17 + l] = v.x;
            Qt[nd][(d + 1) * 17 + l] = v.y;
            Qt[nd][(d + 2) * 17 + l] = v.z;
            Qt[nd][(d + 3) * 17 + l] = v.w;
        } else if (j < 2048) {                // K: raw (broadcast-friendly reads)
            int jj = j - 1024;
            *(float4*)&Ks[nd][jj] = v;
        } else {                              // V: padded Vp[d][g]
            int jj = j - 2048;
            int d = jj >> 4, g = jj & 15;
            Vp[nd][d * 17 + g + 0] = v.x;
            Vp[nd][d * 17 + g + 1] = v.y;
            Vp[nd][d * 17 + g + 2] = v.z;
            Vp[nd][d * 17 + g + 3] = v.w;
        }
    }
    __syncthreads();

    const int nd = tid >> 6;       // node within block
    const int t = tid & 63;
    const int l = t >> 2, gq = t & 3;

    float a0 = 0.f, a1 = 0.f, a2 = 0.f, a3 = 0.f;
#pragma unroll 4
    for (int d = 0; d < 64; d++) {
        float qv = Qt[nd][d * 17 + l];
        const float* kp = &Ks[nd][d * 16 + gq];
        a0 += qv * kp[0];
        a1 += qv * kp[4];
        a2 += qv * kp[8];
        a3 += qv * kp[12];
    }
    const float sc = 0.5f / 64.0f;
    a0 *= sc; a1 *= sc; a2 *= sc; a3 *= sc;

    float mx = fmaxf(fmaxf(a0, a1), fmaxf(a2, a3));
    mx = fmaxf(mx, __shfl_xor_sync(0xffffffffu, mx, 1));
    mx = fmaxf(mx, __shfl_xor_sync(0xffffffffu, mx, 2));
    float e0 = __expf(a0 - mx), e1 = __expf(a1 - mx);
    float e2 = __expf(a2 - mx), e3 = __expf(a3 - mx);
    float s = e0 + e1 + e2 + e3;
    s += __shfl_xor_sync(0xffffffffu, s, 1);
    s += __shfl_xor_sync(0xffffffffu, s, 2);
    float inv = 1.0f / s;
    Ss[nd][l * 17 + gq]      = e0 * inv;
    Ss[nd][l * 17 + gq + 4]  = e1 * inv;
    Ss[nd][l * 17 + gq + 8]  = e2 * inv;
    Ss[nd][l * 17 + gq + 12] = e3 * inv;
    __syncthreads();

    const int d = t;
    float vr[16];
#pragma unroll
    for (int h = 0; h < 16; h++) vr[h] = Vp[nd][d * 17 + h];

    __nv_bfloat162 hib[8], lob[8];
#pragma unroll
    for (int l2 = 0; l2 < 16; l2 += 2) {
        float o0 = 0.f, o1 = 0.f;
#pragma unroll
        for (int h = 0; h < 16; h++) {
            o0 += Ss[nd][l2 * 17 + h] * vr[h];
            o1 += Ss[nd][(l2 + 1) * 17 + h] * vr[h];
        }
        __nv_bfloat16 h0 = __float2bfloat16_rn(o0);
        __nv_bfloat16 h1 = __float2bfloat16_rn(o1);
        float r0 = o0 - __bfloat162float(h0);
        float r1 = o1 - __bfloat162float(h1);
        hib[l2 / 2] = __halves2bfloat162(h0, h1);
        lob[l2 / 2] = __halves2bfloat162(__float2bfloat16_rn(r0), __float2bfloat16_rn(r1));
    }
    size_t base = (node0 + nd) * HID + (size_t)d * 16;   // out_flat[n][d*16+l]
    __nv_bfloat162* ph = (__nv_bfloat162*)(g_o_hi + base);
    __nv_bfloat162* pl = (__nv_bfloat162*)(g_o_lo + base);
#pragma unroll
    for (int p = 0; p < 8; p++) { ph[p] = hib[p]; pl[p] = lob[p]; }
}

// ---------------- entry ------------------------------------------------------
extern "C" void kernel_launch(void* const* d_in, const int* in_sizes, int n_in,
                              void* d_out, int out_size) {
    const float* h   = (const float*)d_in[0];
    const float* Wq  = (const float*)d_in[1];
    const float* Wk  = (const float*)d_in[2];
    const float* Wv  = (const float*)d_in[3];
    const float* Wfc = (const float*)d_in[4];

    k_split_h<<<NN * HID / 4 / 256, 256>>>(h);
    k_split_w1<<<HID * HID / 4 / 256, 256>>>(Wq, 0);
    k_split_w1<<<HID * HID / 4 / 256, 256>>>(Wk, 1);
    k_split_w1<<<HID * HID / 4 / 256, 256>>>(Wv, 2);
    k_split_w2<<<HID * HID / 4 / 256, 256>>>(Wfc);

    cudaFuncSetAttribute(gemm1_kernel, cudaFuncAttributeMaxDynamicSharedMemorySize, SMEM_BYTES);
    cudaFuncSetAttribute(gemm2_kernel, cudaFuncAttributeMaxDynamicSharedMemorySize, SMEM_BYTES);

    gemm1_kernel<<<dim3(NCOLS1 / BN, NN / BM), 256, SMEM_BYTES>>>();
    attn_kernel<<<NN / 2, 128>>>();
    gemm2_kernel<<<dim3(HID / BN, NN / BM), 256, SMEM_BYTES>>>((float*)d_out);
}